// round 9
// baseline (speedup 1.0000x reference)
#include <cuda_runtime.h>
#include <cuda_fp16.h>
#include <math.h>
#include <stdint.h>

#define N_NODES 20000
#define N_EDGES 200000
#define ET      220000    // edges + self loops
#define NFEAT   2048
#define H1      512
#define H2      30

// ------------------------- device scratch -------------------------
__device__ float  g_xw1[(size_t)N_NODES * H1];
__device__ float  g_h1 [(size_t)N_NODES * H1];
__device__ float  g_xw3[(size_t)N_NODES * H1];
__device__ __half g_h3h[(size_t)N_NODES * H1];     // h3 in fp16 (GEMM2 A)
__device__ float  g_h2 [(size_t)N_NODES * H2];
__device__ __half g_feat_h[(size_t)N_NODES * NFEAT]; // features fp16
__device__ __half g_w1_h [(size_t)NFEAT * H1];       // W1 fp16 [2048,512]
__device__ __half g_w1t_h[(size_t)H1 * NFEAT];       // W1^T fp16 [512,2048]
__device__ float  g_a1s[N_NODES];
__device__ float  g_a1d[N_NODES];
__device__ float  g_den[N_NODES];
__device__ int    g_count[N_NODES];
__device__ int    g_cursor[N_NODES];
__device__ int    g_rowptr[N_NODES + 1];
__device__ int    g_srcs[ET];
__device__ float  g_exs[ET];
__device__ double g_mse;

// ------------------------- PTX helpers (base ISA, no 'a' features) ----------
__device__ __forceinline__ uint32_t smem_to_u32(const void* p) {
    uint32_t a;
    asm("{ .reg .u64 t; cvta.to.shared.u64 t, %1; cvt.u32.u64 %0, t; }" : "=r"(a) : "l"(p));
    return a;
}
__device__ __forceinline__ void cp_async16(uint32_t dst, const void* src, int src_bytes) {
    asm volatile("cp.async.ca.shared.global [%0], [%1], 16, %2;"
                 :: "r"(dst), "l"(src), "r"(src_bytes));
}
#define CP_COMMIT() asm volatile("cp.async.commit_group;" ::: "memory")
#define CP_WAIT(n)  asm volatile("cp.async.wait_group %0;" :: "n"(n) : "memory")

__device__ __forceinline__ void ldm_x4(uint32_t& r0, uint32_t& r1, uint32_t& r2, uint32_t& r3,
                                       uint32_t addr) {
    asm volatile("ldmatrix.sync.aligned.m8n8.x4.shared.b16 {%0,%1,%2,%3}, [%4];"
                 : "=r"(r0), "=r"(r1), "=r"(r2), "=r"(r3) : "r"(addr));
}
__device__ __forceinline__ void mma_f16(float c[4], const uint32_t a[4], const uint32_t b[2]) {
    asm volatile(
        "mma.sync.aligned.m16n8k16.row.col.f32.f16.f16.f32 "
        "{%0,%1,%2,%3}, {%4,%5,%6,%7}, {%8,%9}, {%0,%1,%2,%3};"
        : "+f"(c[0]), "+f"(c[1]), "+f"(c[2]), "+f"(c[3])
        : "r"(a[0]), "r"(a[1]), "r"(a[2]), "r"(a[3]), "r"(b[0]), "r"(b[1]));
}

// ------------------------- fp16 NT GEMM (cp.async 4-stage + ldmatrix) ------
// D[M,N] = A[M,K] @ B[N,K]^T, fp16 K-major operands, fp32 accum.
// MSE=false: D -> C.   MSE=true: sum((F - D)^2) -> g_mse.
#define GSTG   4
#define APITCH 40                     // halves per smem row: 32 data + 8 pad (80B)
#define STAGEB (128 * APITCH * 2)     // 10240 B per operand per stage

template<bool MSE>
__global__ __launch_bounds__(256, 2) void hgemm_nt(const __half* __restrict__ A,
                                                   const __half* __restrict__ B,
                                                   float* __restrict__ C,
                                                   const float* __restrict__ F,
                                                   int M, int NN, int K) {
    extern __shared__ char smem[];
    const uint32_t sbase = smem_to_u32(smem);
    const uint32_t smA = sbase;
    const uint32_t smB = sbase + GSTG * STAGEB;
    float* red = (float*)(smem + 2 * GSTG * STAGEB);

    const int tid = threadIdx.x, warp = tid >> 5, lid = tid & 31;
    const int bm = blockIdx.x * 128, bn = blockIdx.y * 128;
    const int wm = (warp & 1) * 64, wn = (warp >> 1) * 32;
    const int KT = K / 32;

    float acc[4][4][4];
#pragma unroll
    for (int mt = 0; mt < 4; mt++)
#pragma unroll
        for (int nt = 0; nt < 4; nt++)
#pragma unroll
            for (int q = 0; q < 4; q++) acc[mt][nt][q] = 0.f;

    // ---- stage issue lambda (manually inlined) ----
    auto issue_stage = [&](int buf, int k0) {
#pragma unroll
        for (int i = 0; i < 2; i++) {
            int id = tid + i * 256;           // 512 16B chunks per operand
            int row = id >> 2, ch = id & 3;
            int gr = bm + row;
            int ok = (gr < M) ? 16 : 0;
            const __half* sa = A + (size_t)(ok ? gr : 0) * K + k0 + ch * 8;
            cp_async16(smA + buf * STAGEB + row * 80 + ch * 16, sa, ok);
            const __half* sb = B + (size_t)(bn + row) * K + k0 + ch * 8;
            cp_async16(smB + buf * STAGEB + row * 80 + ch * 16, sb, 16);
        }
        CP_COMMIT();
    };

    // prologue: stages 0..GSTG-2
#pragma unroll
    for (int s = 0; s < GSTG - 1; s++) issue_stage(s, s * 32);

    for (int kt = 0; kt < KT; kt++) {
        CP_WAIT(GSTG - 2);
        __syncthreads();
        int nxt = kt + GSTG - 1;
        if (nxt < KT) issue_stage(nxt % GSTG, nxt * 32);
        else          CP_COMMIT();           // keep group arithmetic aligned

        const uint32_t sa = smA + (kt % GSTG) * STAGEB;
        const uint32_t sb = smB + (kt % GSTG) * STAGEB;
#pragma unroll
        for (int kh = 0; kh < 2; kh++) {     // two k16 steps per 32-k tile
            uint32_t a[4][4], b[4][2];
#pragma unroll
            for (int mt = 0; mt < 4; mt++) {
                uint32_t addr = sa + (uint32_t)((wm + mt * 16 + (lid & 15)) * 80
                                                + (kh * 16 + (lid >> 4) * 8) * 2);
                ldm_x4(a[mt][0], a[mt][1], a[mt][2], a[mt][3], addr);
            }
#pragma unroll
            for (int ntp = 0; ntp < 2; ntp++) {
                int row_off = ((lid >> 4) << 3) + (lid & 7);
                int kk = kh * 16 + ((lid >> 3) & 1) * 8;
                uint32_t addr = sb + (uint32_t)((wn + ntp * 16 + row_off) * 80 + kk * 2);
                uint32_t r0, r1, r2, r3;
                ldm_x4(r0, r1, r2, r3, addr);
                b[2 * ntp][0] = r0; b[2 * ntp][1] = r1;
                b[2 * ntp + 1][0] = r2; b[2 * ntp + 1][1] = r3;
            }
#pragma unroll
            for (int mt = 0; mt < 4; mt++)
#pragma unroll
                for (int nt = 0; nt < 4; nt++)
                    mma_f16(acc[mt][nt], a[mt], b[nt]);
        }
    }
    __syncthreads();

    if (!MSE) {
#pragma unroll
        for (int mt = 0; mt < 4; mt++) {
            int r0 = bm + wm + mt * 16 + (lid >> 2);
            int r1 = r0 + 8;
#pragma unroll
            for (int nt = 0; nt < 4; nt++) {
                int c = bn + wn + nt * 8 + 2 * (lid & 3);
                if (r0 < M) *(float2*)(C + (size_t)r0 * NN + c) = make_float2(acc[mt][nt][0], acc[mt][nt][1]);
                if (r1 < M) *(float2*)(C + (size_t)r1 * NN + c) = make_float2(acc[mt][nt][2], acc[mt][nt][3]);
            }
        }
    } else {
        float part = 0.f;
#pragma unroll
        for (int mt = 0; mt < 4; mt++) {
            int r0 = bm + wm + mt * 16 + (lid >> 2);
            int r1 = r0 + 8;
#pragma unroll
            for (int nt = 0; nt < 4; nt++) {
                int c = bn + wn + nt * 8 + 2 * (lid & 3);
                if (r0 < M) {
                    float2 f = *(const float2*)(F + (size_t)r0 * NN + c);
                    float d0 = f.x - acc[mt][nt][0], d1 = f.y - acc[mt][nt][1];
                    part = fmaf(d0, d0, part); part = fmaf(d1, d1, part);
                }
                if (r1 < M) {
                    float2 f = *(const float2*)(F + (size_t)r1 * NN + c);
                    float d0 = f.x - acc[mt][nt][2], d1 = f.y - acc[mt][nt][3];
                    part = fmaf(d0, d0, part); part = fmaf(d1, d1, part);
                }
            }
        }
        red[tid] = part;
        __syncthreads();
        for (int o = 128; o > 0; o >>= 1) {
            if (tid < o) red[tid] += red[tid + o];
            __syncthreads();
        }
        if (tid == 0) atomicAdd(&g_mse, (double)red[0]);
    }
}

#define HGEMM_SMEM (2 * GSTG * STAGEB + 1024)

// ------------------------- conversions -------------------------
__global__ void init_kernel() {
    int i = blockIdx.x * blockDim.x + threadIdx.x;
    if (i < N_NODES) { g_den[i] = 0.f; g_count[i] = 0; g_cursor[i] = 0; }
    if (i == 0) g_mse = 0.0;
}

__global__ void cvt_feat(const float* __restrict__ src) {
    int i = blockIdx.x * blockDim.x + threadIdx.x;
    if (i >= (N_NODES * NFEAT) / 4) return;
    float4 v = *(const float4*)(src + (size_t)i * 4);
    __half2 h0 = __floats2half2_rn(v.x, v.y);
    __half2 h1 = __floats2half2_rn(v.z, v.w);
    *(__half2*)(g_feat_h + (size_t)i * 4)     = h0;
    *(__half2*)(g_feat_h + (size_t)i * 4 + 2) = h1;
}

__global__ void cvt_w1(const float* __restrict__ W1) {
    int i = blockIdx.x * blockDim.x + threadIdx.x;
    if (i >= (NFEAT * H1) / 4) return;
    float4 v = *(const float4*)(W1 + (size_t)i * 4);
    *(__half2*)(g_w1_h + (size_t)i * 4)     = __floats2half2_rn(v.x, v.y);
    *(__half2*)(g_w1_h + (size_t)i * 4 + 2) = __floats2half2_rn(v.z, v.w);
}

__global__ __launch_bounds__(256) void transpose_w1_h(const float* __restrict__ W1) {
    __shared__ float t[32][33];
    int bx = blockIdx.x * 32;   // H1
    int by = blockIdx.y * 32;   // NFEAT
    int tx = threadIdx.x & 31, ty = threadIdx.x >> 5;
#pragma unroll
    for (int j = 0; j < 4; j++)
        t[ty + j * 8][tx] = W1[(size_t)(by + ty + j * 8) * H1 + bx + tx];
    __syncthreads();
#pragma unroll
    for (int j = 0; j < 4; j++)
        g_w1t_h[(size_t)(bx + ty + j * 8) * NFEAT + by + tx] = __float2half(t[tx][ty + j * 8]);
}

// ------------------------- attention logits -------------------------
__global__ void att_kernel(const float* __restrict__ att_s, const float* __restrict__ att_d) {
    int gw = (blockIdx.x * blockDim.x + threadIdx.x) >> 5;
    int lane = threadIdx.x & 31;
    if (gw >= N_NODES) return;
    const float* row = g_xw1 + (size_t)gw * H1;
    float ss = 0.f, sd = 0.f;
    for (int k = lane; k < H1; k += 32) {
        float x = row[k];
        ss = fmaf(x, att_s[k], ss);
        sd = fmaf(x, att_d[k], sd);
    }
#pragma unroll
    for (int off = 16; off > 0; off >>= 1) {
        ss += __shfl_xor_sync(0xffffffffu, ss, off);
        sd += __shfl_xor_sync(0xffffffffu, sd, off);
    }
    if (lane == 0) { g_a1s[gw] = ss; g_a1d[gw] = sd; }
}

// ------------------------- CSR build -------------------------
__global__ void count_kernel(const int* __restrict__ ei) {
    int e = blockIdx.x * blockDim.x + threadIdx.x;
    if (e >= ET) return;
    int dst = (e < N_EDGES) ? ei[N_EDGES + e] : (e - N_EDGES);
    atomicAdd(&g_count[dst], 1);
}

__global__ void scan_kernel() {
    __shared__ int part[1024];
    int t = threadIdx.x;
    const int PER = 20;
    int base = t * PER;
    int local[PER];
    int s = 0;
#pragma unroll
    for (int i = 0; i < PER; i++) {
        int idx = base + i;
        int c = (idx < N_NODES) ? g_count[idx] : 0;
        local[i] = s; s += c;
    }
    part[t] = s;
    __syncthreads();
    for (int off = 1; off < 1024; off <<= 1) {
        int v = (t >= off) ? part[t - off] : 0;
        __syncthreads();
        part[t] += v;
        __syncthreads();
    }
    int pre = (t > 0) ? part[t - 1] : 0;
#pragma unroll
    for (int i = 0; i < PER; i++) {
        int idx = base + i;
        if (idx < N_NODES) g_rowptr[idx] = pre + local[i];
    }
    if (t == 1023) g_rowptr[N_NODES] = part[1023];
}

__global__ void fill_kernel(const int* __restrict__ ei) {
    int e = blockIdx.x * blockDim.x + threadIdx.x;
    if (e >= ET) return;
    int src, dst;
    if (e < N_EDGES) { src = ei[e]; dst = ei[N_EDGES + e]; }
    else { src = e - N_EDGES; dst = e - N_EDGES; }
    float z = g_a1s[src] + g_a1d[dst];
    float sg = 1.f / (1.f + expf(-z));
    float ex = expf(sg);                  // softmax numerator (shift-invariant)
    int pos = g_rowptr[dst] + atomicAdd(&g_cursor[dst], 1);
    g_srcs[pos] = src;
    g_exs[pos] = ex;
    atomicAdd(&g_den[dst], ex);
}

// ------------------------- per-dst gather + elu (f32 out) -------------------------
__global__ __launch_bounds__(128) void gather_kernel(const float* __restrict__ X,
                                                     float* __restrict__ Out) {
    int i = blockIdx.x;
    int t = threadIdx.x;
    int beg = g_rowptr[i], end = g_rowptr[i + 1];
    float4 acc = make_float4(0.f, 0.f, 0.f, 0.f);
    for (int j = beg; j < end; j++) {
        int s = g_srcs[j];
        float w = g_exs[j];
        float4 v = *(const float4*)(X + (size_t)s * H1 + t * 4);
        acc.x = fmaf(w, v.x, acc.x);
        acc.y = fmaf(w, v.y, acc.y);
        acc.z = fmaf(w, v.z, acc.z);
        acc.w = fmaf(w, v.w, acc.w);
    }
    float inv = 1.f / g_den[i];
    float4 o;
    float x;
    x = acc.x * inv; o.x = (x > 0.f) ? x : (expf(x) - 1.f);
    x = acc.y * inv; o.y = (x > 0.f) ? x : (expf(x) - 1.f);
    x = acc.z * inv; o.z = (x > 0.f) ? x : (expf(x) - 1.f);
    x = acc.w * inv; o.w = (x > 0.f) ? x : (expf(x) - 1.f);
    *(float4*)(Out + (size_t)i * H1 + t * 4) = o;
}

// ------------------------- gather + elu with fp16 output (for GEMM2 A) ------------
__global__ __launch_bounds__(128) void gather_h_kernel(const float* __restrict__ X) {
    int i = blockIdx.x;
    int t = threadIdx.x;
    int beg = g_rowptr[i], end = g_rowptr[i + 1];
    float4 acc = make_float4(0.f, 0.f, 0.f, 0.f);
    for (int j = beg; j < end; j++) {
        int s = g_srcs[j];
        float w = g_exs[j];
        float4 v = *(const float4*)(X + (size_t)s * H1 + t * 4);
        acc.x = fmaf(w, v.x, acc.x);
        acc.y = fmaf(w, v.y, acc.y);
        acc.z = fmaf(w, v.z, acc.z);
        acc.w = fmaf(w, v.w, acc.w);
    }
    float inv = 1.f / g_den[i];
    float x;
    float4 o;
    x = acc.x * inv; o.x = (x > 0.f) ? x : (expf(x) - 1.f);
    x = acc.y * inv; o.y = (x > 0.f) ? x : (expf(x) - 1.f);
    x = acc.z * inv; o.z = (x > 0.f) ? x : (expf(x) - 1.f);
    x = acc.w * inv; o.w = (x > 0.f) ? x : (expf(x) - 1.f);
    __half2 h0 = __floats2half2_rn(o.x, o.y);
    __half2 h1 = __floats2half2_rn(o.z, o.w);
    *(__half2*)(g_h3h + (size_t)i * H1 + t * 4)     = h0;
    *(__half2*)(g_h3h + (size_t)i * H1 + t * 4 + 2) = h1;
}

// ------------------------- h2 = normalize(h1 @ W2), W2 staged via smem ------------
__global__ __launch_bounds__(256) void h2_kernel(const float* __restrict__ W2) {
    __shared__ float W2s[256 * H2];    // 30720 B
    __shared__ float hrow[8][H1];      // 16384 B
    int w = threadIdx.x >> 5, lane = threadIdx.x & 31;
    int tid = threadIdx.x;
    int r = blockIdx.x * 8 + w;
    bool valid = (r < N_NODES);
    const float* src = valid ? (g_h1 + (size_t)r * H1) : g_h1;
    for (int k = lane; k < H1; k += 32) hrow[w][k] = src[k];

    float val = 0.f;
#pragma unroll
    for (int pass = 0; pass < 2; pass++) {
        __syncthreads();
        for (int idx = tid; idx < 256 * H2; idx += 256)
            W2s[idx] = W2[pass * 256 * H2 + idx];
        __syncthreads();
        if (lane < H2) {
            const float* hr = &hrow[w][pass * 256];
#pragma unroll 8
            for (int k = 0; k < 256; k++)
                val = fmaf(hr[k], W2s[k * H2 + lane], val);
        }
    }
    float sq = (lane < H2) ? val * val : 0.f;
#pragma unroll
    for (int off = 16; off > 0; off >>= 1) sq += __shfl_xor_sync(0xffffffffu, sq, off);
    float norm = sqrtf(sq);
    float inv = 1.f / fmaxf(norm, 1e-12f);
    if (valid && lane < H2) g_h2[(size_t)r * H2 + lane] = val * inv;
}

// ------------------------- xw3 = h2 @ W2^T (small tiled GEMM, fp32) ---------------
#define BM 128
#define BN 128
#define TM 8
#define TN 8
__global__ __launch_bounds__(256) void xw3_gemm(const float* __restrict__ W2) {
    __shared__ float As2[H2][BM + 4];
    __shared__ float Bs2[H2][BN + 4];
    int bm = blockIdx.x * BM, bn = blockIdx.y * BN;
    int tid = threadIdx.x;
    int tr = tid / 16, tc = tid % 16;

    for (int idx = tid; idx < BM * H2; idx += 256) {
        int row = idx / H2, k = idx - row * H2;
        int gr = bm + row;
        As2[k][row] = (gr < N_NODES) ? g_h2[(size_t)gr * H2 + k] : 0.f;
    }
    for (int idx = tid; idx < BN * H2; idx += 256) {
        int c = idx / H2, k = idx - c * H2;
        Bs2[k][c] = W2[(size_t)(bn + c) * H2 + k];
    }
    __syncthreads();

    float acc[TM][TN];
#pragma unroll
    for (int i = 0; i < TM; i++)
#pragma unroll
        for (int j = 0; j < TN; j++) acc[i][j] = 0.f;

#pragma unroll
    for (int k = 0; k < H2; k++) {
        float a[TM], b[TN];
#pragma unroll
        for (int i = 0; i < TM; i++) a[i] = As2[k][tr * TM + i];
#pragma unroll
        for (int j = 0; j < TN; j++) b[j] = Bs2[k][tc * TN + j];
#pragma unroll
        for (int i = 0; i < TM; i++)
#pragma unroll
            for (int j = 0; j < TN; j++) acc[i][j] = fmaf(a[i], b[j], acc[i][j]);
    }

#pragma unroll
    for (int i = 0; i < TM; i++) {
        int gr = bm + tr * TM + i;
        if (gr < N_NODES) {
#pragma unroll
            for (int j = 0; j < TN; j += 4) {
                *(float4*)(g_xw3 + (size_t)gr * H1 + bn + tc * TN + j) =
                    make_float4(acc[i][j], acc[i][j + 1], acc[i][j + 2], acc[i][j + 3]);
            }
        }
    }
}

// ------------------------- finalize -------------------------
__global__ void finalize_kernel(float* out) {
    out[0] = (float)(g_mse * (1.0 / ((double)N_NODES * (double)NFEAT)));
}

// ------------------------- launch -------------------------
extern "C" void kernel_launch(void* const* d_in, const int* in_sizes, int n_in,
                              void* d_out, int out_size) {
    const float* features = (const float*)d_in[0];
    const int*   ei       = (const int*)d_in[1];
    const float* W1       = (const float*)d_in[2];
    const float* att_src1 = (const float*)d_in[3];
    const float* att_dst1 = (const float*)d_in[4];
    const float* W2       = (const float*)d_in[5];
    float* out = (float*)d_out;

    cudaFuncSetAttribute(hgemm_nt<false>, cudaFuncAttributeMaxDynamicSharedMemorySize, HGEMM_SMEM);
    cudaFuncSetAttribute(hgemm_nt<true>,  cudaFuncAttributeMaxDynamicSharedMemorySize, HGEMM_SMEM);

    // 0. init + fp16 conversions
    init_kernel<<<(N_NODES + 255) / 256, 256>>>();
    cvt_feat<<<(N_NODES * NFEAT / 4 + 255) / 256, 256>>>(features);
    cvt_w1<<<(NFEAT * H1 / 4 + 255) / 256, 256>>>(W1);
    {
        dim3 grid(H1 / 32, NFEAT / 32);
        transpose_w1_h<<<grid, 256>>>(W1);
    }

    // 1. xw1 = features @ W1  (fp16 NT: A=feat_h, B=W1^T rows)
    {
        dim3 grid((N_NODES + 127) / 128, H1 / 128);
        hgemm_nt<false><<<grid, 256, HGEMM_SMEM>>>(g_feat_h, g_w1t_h, g_xw1, nullptr,
                                                   N_NODES, H1, NFEAT);
    }

    // 2. attention logits
    att_kernel<<<(N_NODES * 32 + 255) / 256, 256>>>(att_src1, att_dst1);

    // 3. CSR build + edge softmax numerators/denominators
    count_kernel<<<(ET + 255) / 256, 256>>>(ei);
    scan_kernel<<<1, 1024>>>();
    fill_kernel<<<(ET + 255) / 256, 256>>>(ei);

    // 4. h1 = elu(propagate(xw1))
    gather_kernel<<<N_NODES, 128>>>(g_xw1, g_h1);

    // 5. h2 = normalize(h1 @ W2)
    h2_kernel<<<(N_NODES + 7) / 8, 256>>>(W2);

    // 6. xw3 = h2 @ W2^T
    {
        dim3 grid((N_NODES + BM - 1) / BM, H1 / BN);
        xw3_gemm<<<grid, 256>>>(W2);
    }

    // 7. h3 = elu(propagate(xw3)) -> fp16
    gather_h_kernel<<<N_NODES, 128>>>(g_xw3);

    // 8. fused h4 = h3 @ W1^T with MSE (fp16 NT: A=h3_h, B=W1 rows)
    {
        dim3 grid((N_NODES + 127) / 128, NFEAT / 128);
        hgemm_nt<true><<<grid, 256, HGEMM_SMEM>>>(g_h3h, g_w1_h, nullptr, features,
                                                  N_NODES, NFEAT, H1);
    }

    // 9. write scalar
    finalize_kernel<<<1, 1>>>(out);
}

// round 10
// speedup vs baseline: 1.9565x; 1.9565x over previous
#include <cuda_runtime.h>
#include <math.h>
#include <stdint.h>

#define N_NODES 20000
#define N_EDGES 200000
#define ET      220000    // edges + self loops
#define NFEAT   2048
#define H1      512
#define H2      30

// ------------------------- device scratch -------------------------
__device__ float  g_xw1[(size_t)N_NODES * H1];
__device__ float  g_h1 [(size_t)N_NODES * H1];
__device__ float  g_xw3[(size_t)N_NODES * H1];
__device__ float  g_h3 [(size_t)N_NODES * H1];
__device__ float  g_h2 [(size_t)N_NODES * H2];
__device__ float  g_G  [(size_t)H1 * H1];        // W1^T W1  [512,512]
__device__ float  g_a1s[N_NODES];
__device__ float  g_a1d[N_NODES];
__device__ float  g_den[N_NODES];
__device__ int    g_count[N_NODES];
__device__ int    g_cursor[N_NODES];
__device__ int    g_rowptr[N_NODES + 1];
__device__ int    g_srcs[ET];
__device__ float  g_exs[ET];
__device__ double g_sumf2;
__device__ double g_cross;
__device__ double g_quad;

// ------------------------- tf32 helpers -------------------------
__device__ __forceinline__ uint32_t f2tf(float x) {
    uint32_t r;
    asm("cvt.rna.tf32.f32 %0, %1;" : "=r"(r) : "f"(x));
    return r;
}
__device__ __forceinline__ void mma_tf32(float c[4], const uint32_t a[4], const uint32_t b[2]) {
    asm("mma.sync.aligned.m16n8k8.row.col.f32.tf32.tf32.f32 "
        "{%0,%1,%2,%3}, {%4,%5,%6,%7}, {%8,%9}, {%0,%1,%2,%3};"
        : "+f"(c[0]), "+f"(c[1]), "+f"(c[2]), "+f"(c[3])
        : "r"(a[0]), "r"(a[1]), "r"(a[2]), "r"(a[3]), "r"(b[0]), "r"(b[1]));
}

#define BM 128
#define BN 128
#define BK 32
#define SSTR 136
#define SWZ(k, c) ((c) ^ ((((k) >> 2) & 3) << 3))

// ------------------------- init -------------------------
__global__ void init_kernel() {
    int i = blockIdx.x * blockDim.x + threadIdx.x;
    if (i < N_NODES) {
        g_den[i] = 0.f;
        g_count[i] = 0;
        g_cursor[i] = 0;
    }
    if (i == 0) { g_sumf2 = 0.0; g_cross = 0.0; g_quad = 0.0; }
}

// ------------------------- G = W1^T @ W1 (TN, tf32) -------------------------
// A = B = W1 [K=2048 rows, 512 cols] row-major. C[m][n] = sum_k W1[k][m] W1[k][n].
__global__ __launch_bounds__(256, 1) void mm_tn_G(const float* __restrict__ W1) {
    __shared__ uint32_t As[BK][SSTR];
    __shared__ uint32_t Bs[BK][SSTR];
    int bm = blockIdx.x * BM, bn = blockIdx.y * BN;
    int tid = threadIdx.x;
    int warp = tid >> 5, lane = tid & 31;
    int g = lane >> 2, tig = lane & 3;
    int wm = (warp & 1) * 64, wn = (warp >> 1) * 32;

    float acc[4][4][4];
#pragma unroll
    for (int mt = 0; mt < 4; mt++)
#pragma unroll
        for (int nt = 0; nt < 4; nt++)
#pragma unroll
            for (int q = 0; q < 4; q++) acc[mt][nt][q] = 0.f;

    for (int k0 = 0; k0 < NFEAT; k0 += BK) {
#pragma unroll
        for (int it = 0; it < 4; ++it) {
            int p = tid + it * 256;
            int row = p >> 5, c4 = (p & 31) * 4;
            float4 va = *(const float4*)(W1 + (size_t)(k0 + row) * H1 + bm + c4);
            float4 vb = *(const float4*)(W1 + (size_t)(k0 + row) * H1 + bn + c4);
            int col = SWZ(row, c4);
            uint4 ta, tb;
            ta.x = f2tf(va.x); ta.y = f2tf(va.y); ta.z = f2tf(va.z); ta.w = f2tf(va.w);
            tb.x = f2tf(vb.x); tb.y = f2tf(vb.y); tb.z = f2tf(vb.z); tb.w = f2tf(vb.w);
            *(uint4*)&As[row][col] = ta;
            *(uint4*)&Bs[row][col] = tb;
        }
        __syncthreads();
#pragma unroll
        for (int ka = 0; ka < 4; ka++) {
            int kb = ka * 8;
            uint32_t a[4][4], b[4][2];
#pragma unroll
            for (int mt = 0; mt < 4; mt++) {
                int m0 = wm + mt * 16;
                a[mt][0] = As[kb + tig][SWZ(kb + tig, m0 + g)];
                a[mt][1] = As[kb + tig][SWZ(kb + tig, m0 + g + 8)];
                a[mt][2] = As[kb + tig + 4][SWZ(kb + tig + 4, m0 + g)];
                a[mt][3] = As[kb + tig + 4][SWZ(kb + tig + 4, m0 + g + 8)];
            }
#pragma unroll
            for (int nt = 0; nt < 4; nt++) {
                int n0 = wn + nt * 8;
                b[nt][0] = Bs[kb + tig][SWZ(kb + tig, n0 + g)];
                b[nt][1] = Bs[kb + tig + 4][SWZ(kb + tig + 4, n0 + g)];
            }
#pragma unroll
            for (int mt = 0; mt < 4; mt++)
#pragma unroll
                for (int nt = 0; nt < 4; nt++)
                    mma_tf32(acc[mt][nt], a[mt], b[nt]);
        }
        __syncthreads();
    }
#pragma unroll
    for (int mt = 0; mt < 4; mt++) {
        int r0 = bm + wm + mt * 16 + g;
        int r1 = r0 + 8;
#pragma unroll
        for (int nt = 0; nt < 4; nt++) {
            int c = bn + wn + nt * 8 + 2 * tig;
            *(float2*)(g_G + (size_t)r0 * H1 + c) = make_float2(acc[mt][nt][0], acc[mt][nt][1]);
            *(float2*)(g_G + (size_t)r1 * H1 + c) = make_float2(acc[mt][nt][2], acc[mt][nt][3]);
        }
    }
}

// ------------------------- TF32 GEMM NN: C[M,N] = A[M,K] @ B[K,N] -------------------------
__global__ __launch_bounds__(256, 1) void mm_nn_tf32(const float* __restrict__ A,
                                                     const float* __restrict__ B,
                                                     float* __restrict__ C,
                                                     int M, int NN, int K) {
    __shared__ uint32_t As[BK][SSTR];
    __shared__ uint32_t Bs[BK][SSTR];
    int bm = blockIdx.x * BM, bn = blockIdx.y * BN;
    int tid = threadIdx.x;
    int warp = tid >> 5, lane = tid & 31;
    int g = lane >> 2, tig = lane & 3;
    int wm = (warp & 1) * 64, wn = (warp >> 1) * 32;

    float acc[4][4][4];
#pragma unroll
    for (int mt = 0; mt < 4; mt++)
#pragma unroll
        for (int nt = 0; nt < 4; nt++)
#pragma unroll
            for (int q = 0; q < 4; q++) acc[mt][nt][q] = 0.f;

    float4 pa[4], pb[4];
#pragma unroll
    for (int it = 0; it < 4; ++it) {
        int p = tid + it * 256;
        int arow = p >> 3, akq = (p & 7) * 4;
        int gr = bm + arow;
        pa[it] = make_float4(0.f, 0.f, 0.f, 0.f);
        if (gr < M) pa[it] = *(const float4*)(A + (size_t)gr * K + akq);
        int brow = p >> 5, bc4 = (p & 31) * 4;
        pb[it] = *(const float4*)(B + (size_t)brow * NN + bn + bc4);
    }

    for (int k0 = 0; k0 < K; k0 += BK) {
#pragma unroll
        for (int it = 0; it < 4; ++it) {
            int p = tid + it * 256;
            int arow = p >> 3, akq = (p & 7) * 4;
            As[akq + 0][SWZ(akq + 0, arow)] = f2tf(pa[it].x);
            As[akq + 1][SWZ(akq + 1, arow)] = f2tf(pa[it].y);
            As[akq + 2][SWZ(akq + 2, arow)] = f2tf(pa[it].z);
            As[akq + 3][SWZ(akq + 3, arow)] = f2tf(pa[it].w);
            int brow = p >> 5, bc4 = (p & 31) * 4;
            int col = SWZ(brow, bc4);
            uint4 v;
            v.x = f2tf(pb[it].x); v.y = f2tf(pb[it].y);
            v.z = f2tf(pb[it].z); v.w = f2tf(pb[it].w);
            *(uint4*)&Bs[brow][col] = v;
        }
        __syncthreads();

        int kn = k0 + BK;
        if (kn < K) {
#pragma unroll
            for (int it = 0; it < 4; ++it) {
                int p = tid + it * 256;
                int arow = p >> 3, akq = (p & 7) * 4;
                int gr = bm + arow;
                pa[it] = make_float4(0.f, 0.f, 0.f, 0.f);
                if (gr < M) pa[it] = *(const float4*)(A + (size_t)gr * K + kn + akq);
                int brow = p >> 5, bc4 = (p & 31) * 4;
                pb[it] = *(const float4*)(B + (size_t)(kn + brow) * NN + bn + bc4);
            }
        }

#pragma unroll
        for (int ka = 0; ka < 4; ka++) {
            int kb = ka * 8;
            uint32_t a[4][4], b[4][2];
#pragma unroll
            for (int mt = 0; mt < 4; mt++) {
                int m0 = wm + mt * 16;
                a[mt][0] = As[kb + tig][SWZ(kb + tig, m0 + g)];
                a[mt][1] = As[kb + tig][SWZ(kb + tig, m0 + g + 8)];
                a[mt][2] = As[kb + tig + 4][SWZ(kb + tig + 4, m0 + g)];
                a[mt][3] = As[kb + tig + 4][SWZ(kb + tig + 4, m0 + g + 8)];
            }
#pragma unroll
            for (int nt = 0; nt < 4; nt++) {
                int n0 = wn + nt * 8;
                b[nt][0] = Bs[kb + tig][SWZ(kb + tig, n0 + g)];
                b[nt][1] = Bs[kb + tig + 4][SWZ(kb + tig + 4, n0 + g)];
            }
#pragma unroll
            for (int mt = 0; mt < 4; mt++)
#pragma unroll
                for (int nt = 0; nt < 4; nt++)
                    mma_tf32(acc[mt][nt], a[mt], b[nt]);
        }
        __syncthreads();
    }

#pragma unroll
    for (int mt = 0; mt < 4; mt++) {
        int r0 = bm + wm + mt * 16 + g;
        int r1 = r0 + 8;
#pragma unroll
        for (int nt = 0; nt < 4; nt++) {
            int c = bn + wn + nt * 8 + 2 * tig;
            if (r0 < M) *(float2*)(C + (size_t)r0 * NN + c) = make_float2(acc[mt][nt][0], acc[mt][nt][1]);
            if (r1 < M) *(float2*)(C + (size_t)r1 * NN + c) = make_float2(acc[mt][nt][2], acc[mt][nt][3]);
        }
    }
}

// ------------------------- quad GEMM: S = h3 @ G, reduce sum(h3 .* S) ------------
// A = g_h3 [M=20000, K=512], B = g_G [512, 512]. Nothing stored; epilogue reads h3
// back (L2-resident) and accumulates the quadratic term into g_quad.
__global__ __launch_bounds__(256, 1) void mm_nn_quad(int M) {
    __shared__ uint32_t As[BK][SSTR];
    __shared__ uint32_t Bs[BK][SSTR];
    __shared__ float red[256];
    const float* A = g_h3;
    const float* B = g_G;
    const int NN = H1, K = H1;
    int bm = blockIdx.x * BM, bn = blockIdx.y * BN;
    int tid = threadIdx.x;
    int warp = tid >> 5, lane = tid & 31;
    int g = lane >> 2, tig = lane & 3;
    int wm = (warp & 1) * 64, wn = (warp >> 1) * 32;

    float acc[4][4][4];
#pragma unroll
    for (int mt = 0; mt < 4; mt++)
#pragma unroll
        for (int nt = 0; nt < 4; nt++)
#pragma unroll
            for (int q = 0; q < 4; q++) acc[mt][nt][q] = 0.f;

    for (int k0 = 0; k0 < K; k0 += BK) {
#pragma unroll
        for (int it = 0; it < 4; ++it) {
            int p = tid + it * 256;
            int arow = p >> 3, akq = (p & 7) * 4;
            int gr = bm + arow;
            float4 va = make_float4(0.f, 0.f, 0.f, 0.f);
            if (gr < M) va = *(const float4*)(A + (size_t)gr * K + k0 + akq);
            As[akq + 0][SWZ(akq + 0, arow)] = f2tf(va.x);
            As[akq + 1][SWZ(akq + 1, arow)] = f2tf(va.y);
            As[akq + 2][SWZ(akq + 2, arow)] = f2tf(va.z);
            As[akq + 3][SWZ(akq + 3, arow)] = f2tf(va.w);
            int brow = p >> 5, bc4 = (p & 31) * 4;
            float4 vb = *(const float4*)(B + (size_t)(k0 + brow) * NN + bn + bc4);
            int col = SWZ(brow, bc4);
            uint4 tv;
            tv.x = f2tf(vb.x); tv.y = f2tf(vb.y); tv.z = f2tf(vb.z); tv.w = f2tf(vb.w);
            *(uint4*)&Bs[brow][col] = tv;
        }
        __syncthreads();
#pragma unroll
        for (int ka = 0; ka < 4; ka++) {
            int kb = ka * 8;
            uint32_t a[4][4], b[4][2];
#pragma unroll
            for (int mt = 0; mt < 4; mt++) {
                int m0 = wm + mt * 16;
                a[mt][0] = As[kb + tig][SWZ(kb + tig, m0 + g)];
                a[mt][1] = As[kb + tig][SWZ(kb + tig, m0 + g + 8)];
                a[mt][2] = As[kb + tig + 4][SWZ(kb + tig + 4, m0 + g)];
                a[mt][3] = As[kb + tig + 4][SWZ(kb + tig + 4, m0 + g + 8)];
            }
#pragma unroll
            for (int nt = 0; nt < 4; nt++) {
                int n0 = wn + nt * 8;
                b[nt][0] = Bs[kb + tig][SWZ(kb + tig, n0 + g)];
                b[nt][1] = Bs[kb + tig + 4][SWZ(kb + tig + 4, n0 + g)];
            }
#pragma unroll
            for (int mt = 0; mt < 4; mt++)
#pragma unroll
                for (int nt = 0; nt < 4; nt++)
                    mma_tf32(acc[mt][nt], a[mt], b[nt]);
        }
        __syncthreads();
    }

    // epilogue: quad partial = sum over tile of S .* h3
    float part = 0.f;
#pragma unroll
    for (int mt = 0; mt < 4; mt++) {
        int r0 = bm + wm + mt * 16 + g;
        int r1 = r0 + 8;
#pragma unroll
        for (int nt = 0; nt < 4; nt++) {
            int c = bn + wn + nt * 8 + 2 * tig;
            if (r0 < M) {
                float2 h = *(const float2*)(g_h3 + (size_t)r0 * H1 + c);
                part = fmaf(acc[mt][nt][0], h.x, part);
                part = fmaf(acc[mt][nt][1], h.y, part);
            }
            if (r1 < M) {
                float2 h = *(const float2*)(g_h3 + (size_t)r1 * H1 + c);
                part = fmaf(acc[mt][nt][2], h.x, part);
                part = fmaf(acc[mt][nt][3], h.y, part);
            }
        }
    }
    red[tid] = part;
    __syncthreads();
    for (int o = 128; o > 0; o >>= 1) {
        if (tid < o) red[tid] += red[tid + o];
        __syncthreads();
    }
    if (tid == 0) atomicAdd(&g_quad, (double)red[0]);
}

// ------------------------- sum(features^2) -------------------------
__global__ __launch_bounds__(256) void sumf2_kernel(const float* __restrict__ f) {
    __shared__ float red[256];
    const size_t total4 = (size_t)N_NODES * NFEAT / 4;
    size_t idx = (size_t)blockIdx.x * blockDim.x + threadIdx.x;
    size_t stride = (size_t)gridDim.x * blockDim.x;
    float part = 0.f;
    for (size_t i = idx; i < total4; i += stride) {
        float4 v = ((const float4*)f)[i];
        part = fmaf(v.x, v.x, part);
        part = fmaf(v.y, v.y, part);
        part = fmaf(v.z, v.z, part);
        part = fmaf(v.w, v.w, part);
    }
    red[threadIdx.x] = part;
    __syncthreads();
    for (int o = 128; o > 0; o >>= 1) {
        if (threadIdx.x < o) red[threadIdx.x] += red[threadIdx.x + o];
        __syncthreads();
    }
    if (threadIdx.x == 0) atomicAdd(&g_sumf2, (double)red[0]);
}

// ------------------------- attention logits -------------------------
__global__ void att_kernel(const float* __restrict__ att_s, const float* __restrict__ att_d) {
    int gw = (blockIdx.x * blockDim.x + threadIdx.x) >> 5;
    int lane = threadIdx.x & 31;
    if (gw >= N_NODES) return;
    const float* row = g_xw1 + (size_t)gw * H1;
    float ss = 0.f, sd = 0.f;
    for (int k = lane; k < H1; k += 32) {
        float x = row[k];
        ss = fmaf(x, att_s[k], ss);
        sd = fmaf(x, att_d[k], sd);
    }
#pragma unroll
    for (int off = 16; off > 0; off >>= 1) {
        ss += __shfl_xor_sync(0xffffffffu, ss, off);
        sd += __shfl_xor_sync(0xffffffffu, sd, off);
    }
    if (lane == 0) { g_a1s[gw] = ss; g_a1d[gw] = sd; }
}

// ------------------------- CSR build -------------------------
__global__ void count_kernel(const int* __restrict__ ei) {
    int e = blockIdx.x * blockDim.x + threadIdx.x;
    if (e >= ET) return;
    int dst = (e < N_EDGES) ? ei[N_EDGES + e] : (e - N_EDGES);
    atomicAdd(&g_count[dst], 1);
}

__global__ void scan_kernel() {
    __shared__ int part[1024];
    int t = threadIdx.x;
    const int PER = 20;
    int base = t * PER;
    int local[PER];
    int s = 0;
#pragma unroll
    for (int i = 0; i < PER; i++) {
        int idx = base + i;
        int c = (idx < N_NODES) ? g_count[idx] : 0;
        local[i] = s; s += c;
    }
    part[t] = s;
    __syncthreads();
    for (int off = 1; off < 1024; off <<= 1) {
        int v = (t >= off) ? part[t - off] : 0;
        __syncthreads();
        part[t] += v;
        __syncthreads();
    }
    int pre = (t > 0) ? part[t - 1] : 0;
#pragma unroll
    for (int i = 0; i < PER; i++) {
        int idx = base + i;
        if (idx < N_NODES) g_rowptr[idx] = pre + local[i];
    }
    if (t == 1023) g_rowptr[N_NODES] = part[1023];
}

__global__ void fill_kernel(const int* __restrict__ ei) {
    int e = blockIdx.x * blockDim.x + threadIdx.x;
    if (e >= ET) return;
    int src, dst;
    if (e < N_EDGES) { src = ei[e]; dst = ei[N_EDGES + e]; }
    else { src = e - N_EDGES; dst = e - N_EDGES; }
    float z = g_a1s[src] + g_a1d[dst];
    float sg = 1.f / (1.f + expf(-z));
    float ex = expf(sg);                  // softmax numerator (shift-invariant)
    int pos = g_rowptr[dst] + atomicAdd(&g_cursor[dst], 1);
    g_srcs[pos] = src;
    g_exs[pos] = ex;
    atomicAdd(&g_den[dst], ex);
}

// ------------------------- per-dst gather + elu -------------------------
__global__ __launch_bounds__(128) void gather_kernel(const float* __restrict__ X,
                                                     float* __restrict__ Out) {
    int i = blockIdx.x;
    int t = threadIdx.x;
    int beg = g_rowptr[i], end = g_rowptr[i + 1];
    float4 acc = make_float4(0.f, 0.f, 0.f, 0.f);
    for (int j = beg; j < end; j++) {
        int s = g_srcs[j];
        float w = g_exs[j];
        float4 v = *(const float4*)(X + (size_t)s * H1 + t * 4);
        acc.x = fmaf(w, v.x, acc.x);
        acc.y = fmaf(w, v.y, acc.y);
        acc.z = fmaf(w, v.z, acc.z);
        acc.w = fmaf(w, v.w, acc.w);
    }
    float inv = 1.f / g_den[i];
    float4 o;
    float x;
    x = acc.x * inv; o.x = (x > 0.f) ? x : (expf(x) - 1.f);
    x = acc.y * inv; o.y = (x > 0.f) ? x : (expf(x) - 1.f);
    x = acc.z * inv; o.z = (x > 0.f) ? x : (expf(x) - 1.f);
    x = acc.w * inv; o.w = (x > 0.f) ? x : (expf(x) - 1.f);
    *(float4*)(Out + (size_t)i * H1 + t * 4) = o;
}

// ------------------------- gather #2: h3 + cross-term sum(h3 .* xw1) ---------------
__global__ __launch_bounds__(128) void gather2_kernel(const float* __restrict__ X) {
    __shared__ float red[128];
    int i = blockIdx.x;
    int t = threadIdx.x;
    int beg = g_rowptr[i], end = g_rowptr[i + 1];
    float4 acc = make_float4(0.f, 0.f, 0.f, 0.f);
    for (int j = beg; j < end; j++) {
        int s = g_srcs[j];
        float w = g_exs[j];
        float4 v = *(const float4*)(X + (size_t)s * H1 + t * 4);
        acc.x = fmaf(w, v.x, acc.x);
        acc.y = fmaf(w, v.y, acc.y);
        acc.z = fmaf(w, v.z, acc.z);
        acc.w = fmaf(w, v.w, acc.w);
    }
    float inv = 1.f / g_den[i];
    float4 o;
    float x;
    x = acc.x * inv; o.x = (x > 0.f) ? x : (expf(x) - 1.f);
    x = acc.y * inv; o.y = (x > 0.f) ? x : (expf(x) - 1.f);
    x = acc.z * inv; o.z = (x > 0.f) ? x : (expf(x) - 1.f);
    x = acc.w * inv; o.w = (x > 0.f) ? x : (expf(x) - 1.f);
    *(float4*)(g_h3 + (size_t)i * H1 + t * 4) = o;

    // cross term: h3[i][:] . xw1[i][:]
    float4 x1 = *(const float4*)(g_xw1 + (size_t)i * H1 + t * 4);
    float part = o.x * x1.x + o.y * x1.y + o.z * x1.z + o.w * x1.w;
    red[t] = part;
    __syncthreads();
    for (int off = 64; off > 0; off >>= 1) {
        if (t < off) red[t] += red[t + off];
        __syncthreads();
    }
    if (t == 0) atomicAdd(&g_cross, (double)red[0]);
}

// ------------------------- h2 = normalize(h1 @ W2), W2 staged via smem ------------
__global__ __launch_bounds__(256) void h2_kernel(const float* __restrict__ W2) {
    __shared__ float W2s[256 * H2];
    __shared__ float hrow[8][H1];
    int w = threadIdx.x >> 5, lane = threadIdx.x & 31;
    int tid = threadIdx.x;
    int r = blockIdx.x * 8 + w;
    bool valid = (r < N_NODES);
    const float* src = valid ? (g_h1 + (size_t)r * H1) : g_h1;
    for (int k = lane; k < H1; k += 32) hrow[w][k] = src[k];

    float val = 0.f;
#pragma unroll
    for (int pass = 0; pass < 2; pass++) {
        __syncthreads();
        for (int idx = tid; idx < 256 * H2; idx += 256)
            W2s[idx] = W2[pass * 256 * H2 + idx];
        __syncthreads();
        if (lane < H2) {
            const float* hr = &hrow[w][pass * 256];
#pragma unroll 8
            for (int k = 0; k < 256; k++)
                val = fmaf(hr[k], W2s[k * H2 + lane], val);
        }
    }
    float sq = (lane < H2) ? val * val : 0.f;
#pragma unroll
    for (int off = 16; off > 0; off >>= 1) sq += __shfl_xor_sync(0xffffffffu, sq, off);
    float norm = sqrtf(sq);
    float inv = 1.f / fmaxf(norm, 1e-12f);
    if (valid && lane < H2) g_h2[(size_t)r * H2 + lane] = val * inv;
}

// ------------------------- xw3 = h2 @ W2^T (small tiled GEMM) ---------------------
#define TM 8
#define TN 8
__global__ __launch_bounds__(256) void xw3_gemm(const float* __restrict__ W2) {
    __shared__ float As2[H2][BM + 4];
    __shared__ float Bs2[H2][BN + 4];
    int bm = blockIdx.x * BM, bn = blockIdx.y * BN;
    int tid = threadIdx.x;
    int tr = tid / 16, tc = tid % 16;

    for (int idx = tid; idx < BM * H2; idx += 256) {
        int row = idx / H2, k = idx - row * H2;
        int gr = bm + row;
        As2[k][row] = (gr < N_NODES) ? g_h2[(size_t)gr * H2 + k] : 0.f;
    }
    for (int idx = tid; idx < BN * H2; idx += 256) {
        int c = idx / H2, k = idx - c * H2;
        Bs2[k][c] = W2[(size_t)(bn + c) * H2 + k];
    }
    __syncthreads();

    float acc[TM][TN];
#pragma unroll
    for (int i = 0; i < TM; i++)
#pragma unroll
        for (int j = 0; j < TN; j++) acc[i][j] = 0.f;

#pragma unroll
    for (int k = 0; k < H2; k++) {
        float a[TM], b[TN];
#pragma unroll
        for (int i = 0; i < TM; i++) a[i] = As2[k][tr * TM + i];
#pragma unroll
        for (int j = 0; j < TN; j++) b[j] = Bs2[k][tc * TN + j];
#pragma unroll
        for (int i = 0; i < TM; i++)
#pragma unroll
            for (int j = 0; j < TN; j++) acc[i][j] = fmaf(a[i], b[j], acc[i][j]);
    }

#pragma unroll
    for (int i = 0; i < TM; i++) {
        int gr = bm + tr * TM + i;
        if (gr < N_NODES) {
#pragma unroll
            for (int j = 0; j < TN; j += 4) {
                *(float4*)(g_xw3 + (size_t)gr * H1 + bn + tc * TN + j) =
                    make_float4(acc[i][j], acc[i][j + 1], acc[i][j + 2], acc[i][j + 3]);
            }
        }
    }
}

// ------------------------- finalize -------------------------
__global__ void finalize_kernel(float* out) {
    double mse = (g_sumf2 - 2.0 * g_cross + g_quad) * (1.0 / ((double)N_NODES * (double)NFEAT));
    out[0] = (float)mse;
}

// ------------------------- launch -------------------------
extern "C" void kernel_launch(void* const* d_in, const int* in_sizes, int n_in,
                              void* d_out, int out_size) {
    const float* features = (const float*)d_in[0];
    const int*   ei       = (const int*)d_in[1];
    const float* W1       = (const float*)d_in[2];
    const float* att_src1 = (const float*)d_in[3];
    const float* att_dst1 = (const float*)d_in[4];
    const float* W2       = (const float*)d_in[5];
    float* out = (float*)d_out;

    // 1. init
    init_kernel<<<(N_NODES + 255) / 256, 256>>>();

    // 2. G = W1^T W1 (tiny, 1 GFLOP)
    {
        dim3 grid(H1 / BM, H1 / BN);
        mm_tn_G<<<grid, 256>>>(W1);
    }

    // 3. CSR count (independent)
    count_kernel<<<(ET + 255) / 256, 256>>>(ei);

    // 4. xw1 = features @ W1  (42 GFLOP)  <-- profiled launch slot
    {
        dim3 grid((N_NODES + BM - 1) / BM, H1 / BN);
        mm_nn_tf32<<<grid, 256>>>(features, W1, g_xw1, N_NODES, H1, NFEAT);
    }

    // 5. attention logits
    att_kernel<<<(N_NODES * 32 + 255) / 256, 256>>>(att_src1, att_dst1);

    // 6. CSR scan
    scan_kernel<<<1, 1024>>>();

    // 7. sum(features^2) (independent)
    sumf2_kernel<<<2048, 256>>>(features);

    // 8. CSR fill + softmax numerators
    fill_kernel<<<(ET + 255) / 256, 256>>>(ei);

    // 9. h1 = elu(propagate(xw1))
    gather_kernel<<<N_NODES, 128>>>(g_xw1, g_h1);

    // 10. h2 = normalize(h1 @ W2)
    h2_kernel<<<(N_NODES + 7) / 8, 256>>>(W2);

    // 11. xw3 = h2 @ W2^T
    {
        dim3 grid((N_NODES + BM - 1) / BM, H1 / BN);
        xw3_gemm<<<grid, 256>>>(W2);
    }

    // 12. h3 = elu(propagate(xw3)) + cross term vs xw1
    gather2_kernel<<<N_NODES, 128>>>(g_xw3);

    // 13. quad term: sum(h3 .* (h3 @ G))  (10.5 GFLOP)
    {
        dim3 grid((N_NODES + BM - 1) / BM, H1 / BN);
        mm_nn_quad<<<grid, 256>>>(N_NODES);
    }

    // 14. mse = (sumf2 - 2*cross + quad) / (N*F)
    finalize_kernel<<<1, 1>>>(out);
}

// round 11
// speedup vs baseline: 2.1579x; 1.1029x over previous
#include <cuda_runtime.h>
#include <math.h>
#include <stdint.h>

#define N_NODES 20000
#define N_EDGES 200000
#define ET      220000
#define NFEAT   2048
#define H1      512
#define H2      30

// ------------------------- device scratch -------------------------
__device__ float  g_xw1[(size_t)N_NODES * H1];
__device__ float  g_h1 [(size_t)N_NODES * H1];
__device__ float  g_xw3[(size_t)N_NODES * H1];
__device__ float  g_h3 [(size_t)N_NODES * H1];
__device__ float  g_G  [(size_t)H1 * H1];
__device__ float  g_a1s[N_NODES];
__device__ float  g_a1d[N_NODES];
__device__ float  g_den[N_NODES];
__device__ int    g_count[N_NODES];
__device__ int    g_cursor[N_NODES];
__device__ int    g_rowptr[N_NODES + 1];
__device__ int    g_srcs[ET];
__device__ float  g_exs[ET];
__device__ double g_sumf2;
__device__ double g_cross;
__device__ double g_quad;

// ------------------------- helpers -------------------------
__device__ __forceinline__ uint32_t smem_to_u32(const void* p) {
    uint32_t a;
    asm("{ .reg .u64 t; cvta.to.shared.u64 t, %1; cvt.u32.u64 %0, t; }" : "=r"(a) : "l"(p));
    return a;
}
__device__ __forceinline__ uint32_t f2tf(float x) {
    uint32_t r;
    asm("cvt.rna.tf32.f32 %0, %1;" : "=r"(r) : "f"(x));
    return r;
}
__device__ __forceinline__ void mma_tf32(float c[4], const uint32_t a[4], const uint32_t b[2]) {
    asm("mma.sync.aligned.m16n8k8.row.col.f32.tf32.tf32.f32 "
        "{%0,%1,%2,%3}, {%4,%5,%6,%7}, {%8,%9}, {%0,%1,%2,%3};"
        : "+f"(c[0]), "+f"(c[1]), "+f"(c[2]), "+f"(c[3])
        : "r"(a[0]), "r"(a[1]), "r"(a[2]), "r"(a[3]), "r"(b[0]), "r"(b[1]));
}
__device__ __forceinline__ void cp_async16(uint32_t dst, const void* src, int src_bytes) {
    asm volatile("cp.async.ca.shared.global [%0], [%1], 16, %2;"
                 :: "r"(dst), "l"(src), "r"(src_bytes));
}
#define CP_COMMIT() asm volatile("cp.async.commit_group;" ::: "memory")
#define CP_WAIT1()  asm volatile("cp.async.wait_group 1;" ::: "memory")

// pipelined GEMM geometry
#define BM 128
#define BN 128
#define BK 32
#define APF 36           // A smem pitch (floats): banks (4g+tig) distinct
#define BPF 136          // B smem pitch (floats): banks (8tig+g) distinct
#define A_BYTES (BM * APF * 4)          // 18432
#define B_BYTES (BK * BPF * 4)          // 17408
#define STG_BYTES (A_BYTES + B_BYTES)   // 35840
#define NSTG 3
#define PIPE_SMEM (NSTG * STG_BYTES)    // 107520

// old-style swizzle for the tiny G kernel
#define SSTR 136
#define SWZ(k, c) ((c) ^ ((((k) >> 2) & 3) << 3))

// ------------------------- init -------------------------
__global__ void init_kernel() {
    int i = blockIdx.x * blockDim.x + threadIdx.x;
    if (i < N_NODES) {
        g_den[i] = 0.f; g_count[i] = 0; g_cursor[i] = 0;
        g_a1s[i] = 0.f; g_a1d[i] = 0.f;
    }
    if (i == 0) { g_sumf2 = 0.0; g_cross = 0.0; g_quad = 0.0; }
}

// ------------------------- G = W1^T @ W1 (tiny, single-buffered) ----------------
__global__ __launch_bounds__(256, 1) void mm_tn_G(const float* __restrict__ W1) {
    __shared__ uint32_t As[BK][SSTR];
    __shared__ uint32_t Bs[BK][SSTR];
    int bm = blockIdx.x * BM, bn = blockIdx.y * BN;
    int tid = threadIdx.x;
    int warp = tid >> 5, lane = tid & 31;
    int g = lane >> 2, tig = lane & 3;
    int wm = (warp & 1) * 64, wn = (warp >> 1) * 32;

    float acc[4][4][4];
#pragma unroll
    for (int mt = 0; mt < 4; mt++)
#pragma unroll
        for (int nt = 0; nt < 4; nt++)
#pragma unroll
            for (int q = 0; q < 4; q++) acc[mt][nt][q] = 0.f;

    for (int k0 = 0; k0 < NFEAT; k0 += BK) {
#pragma unroll
        for (int it = 0; it < 4; ++it) {
            int p = tid + it * 256;
            int row = p >> 5, c4 = (p & 31) * 4;
            float4 va = *(const float4*)(W1 + (size_t)(k0 + row) * H1 + bm + c4);
            float4 vb = *(const float4*)(W1 + (size_t)(k0 + row) * H1 + bn + c4);
            int col = SWZ(row, c4);
            uint4 ta, tb;
            ta.x = f2tf(va.x); ta.y = f2tf(va.y); ta.z = f2tf(va.z); ta.w = f2tf(va.w);
            tb.x = f2tf(vb.x); tb.y = f2tf(vb.y); tb.z = f2tf(vb.z); tb.w = f2tf(vb.w);
            *(uint4*)&As[row][col] = ta;
            *(uint4*)&Bs[row][col] = tb;
        }
        __syncthreads();
#pragma unroll
        for (int ka = 0; ka < 4; ka++) {
            int kb = ka * 8;
            uint32_t a[4][4], b[4][2];
#pragma unroll
            for (int mt = 0; mt < 4; mt++) {
                int m0 = wm + mt * 16;
                a[mt][0] = As[kb + tig][SWZ(kb + tig, m0 + g)];
                a[mt][1] = As[kb + tig][SWZ(kb + tig, m0 + g + 8)];
                a[mt][2] = As[kb + tig + 4][SWZ(kb + tig + 4, m0 + g)];
                a[mt][3] = As[kb + tig + 4][SWZ(kb + tig + 4, m0 + g + 8)];
            }
#pragma unroll
            for (int nt = 0; nt < 4; nt++) {
                int n0 = wn + nt * 8;
                b[nt][0] = Bs[kb + tig][SWZ(kb + tig, n0 + g)];
                b[nt][1] = Bs[kb + tig + 4][SWZ(kb + tig + 4, n0 + g)];
            }
#pragma unroll
            for (int mt = 0; mt < 4; mt++)
#pragma unroll
                for (int nt = 0; nt < 4; nt++)
                    mma_tf32(acc[mt][nt], a[mt], b[nt]);
        }
        __syncthreads();
    }
#pragma unroll
    for (int mt = 0; mt < 4; mt++) {
        int r0 = bm + wm + mt * 16 + g;
        int r1 = r0 + 8;
#pragma unroll
        for (int nt = 0; nt < 4; nt++) {
            int c = bn + wn + nt * 8 + 2 * tig;
            *(float2*)(g_G + (size_t)r0 * H1 + c) = make_float2(acc[mt][nt][0], acc[mt][nt][1]);
            *(float2*)(g_G + (size_t)r1 * H1 + c) = make_float2(acc[mt][nt][2], acc[mt][nt][3]);
        }
    }
}

// ------------------------- pipelined tf32 GEMM NN + fused att epilogue ----------
// C = A[M,K] @ B[K,N]; also a1s[r] += C[r,:].att_s, a1d likewise (atomics).
__global__ __launch_bounds__(256, 2) void mm_xw1_att(const float* __restrict__ A,
                                                     const float* __restrict__ B,
                                                     float* __restrict__ C,
                                                     const float* __restrict__ att_s,
                                                     const float* __restrict__ att_d,
                                                     int M, int NN, int K) {
    extern __shared__ char smem[];
    const uint32_t sb = smem_to_u32(smem);
    const int tid = threadIdx.x;
    const int warp = tid >> 5, lane = tid & 31;
    const int g = lane >> 2, tig = lane & 3;
    const int wm = (warp & 1) * 64, wn = (warp >> 1) * 32;
    const int bm = blockIdx.x * BM, bn = blockIdx.y * BN;
    const int KT = K / BK;

    float acc[4][4][4];
#pragma unroll
    for (int mt = 0; mt < 4; mt++)
#pragma unroll
        for (int nt = 0; nt < 4; nt++)
#pragma unroll
            for (int q = 0; q < 4; q++) acc[mt][nt][q] = 0.f;

#define ISSUE_STAGE(buf, k0) do {                                              \
    uint32_t _sA = sb + (buf) * STG_BYTES;                                     \
    uint32_t _sB = _sA + A_BYTES;                                              \
    _Pragma("unroll")                                                          \
    for (int _i = 0; _i < 4; _i++) {                                           \
        int _id = tid + _i * 256;                                              \
        int _row = _id >> 3, _ch = _id & 7;                                    \
        int _gr = bm + _row;                                                   \
        int _ok = (_gr < M) ? 16 : 0;                                          \
        cp_async16(_sA + _row * (APF * 4) + _ch * 16,                          \
                   A + (size_t)(_ok ? _gr : 0) * K + (k0) + _ch * 4, _ok);     \
        int _br = _id >> 5, _bc = _id & 31;                                    \
        cp_async16(_sB + _br * (BPF * 4) + _bc * 16,                           \
                   B + (size_t)((k0) + _br) * NN + bn + _bc * 4, 16);          \
    }                                                                          \
    CP_COMMIT();                                                               \
} while (0)

    ISSUE_STAGE(0, 0);
    ISSUE_STAGE(1, BK);

    for (int kt = 0; kt < KT; kt++) {
        CP_WAIT1();
        __syncthreads();
        int nxt = kt + 2;
        if (nxt < KT) { ISSUE_STAGE(nxt % NSTG, nxt * BK); }
        else          { CP_COMMIT(); }

        const float* As_f = (const float*)(smem + (kt % NSTG) * STG_BYTES);
        const float* Bs_f = (const float*)(smem + (kt % NSTG) * STG_BYTES + A_BYTES);
#pragma unroll
        for (int ka = 0; ka < 4; ka++) {
            int kb = ka * 8;
            uint32_t a[4][4], b[4][2];
#pragma unroll
            for (int mt = 0; mt < 4; mt++) {
                int m0 = wm + mt * 16 + g;
                a[mt][0] = f2tf(As_f[m0 * APF + kb + tig]);
                a[mt][1] = f2tf(As_f[(m0 + 8) * APF + kb + tig]);
                a[mt][2] = f2tf(As_f[m0 * APF + kb + tig + 4]);
                a[mt][3] = f2tf(As_f[(m0 + 8) * APF + kb + tig + 4]);
            }
#pragma unroll
            for (int nt = 0; nt < 4; nt++) {
                int n0 = wn + nt * 8 + g;
                b[nt][0] = f2tf(Bs_f[(kb + tig) * BPF + n0]);
                b[nt][1] = f2tf(Bs_f[(kb + tig + 4) * BPF + n0]);
            }
#pragma unroll
            for (int mt = 0; mt < 4; mt++)
#pragma unroll
                for (int nt = 0; nt < 4; nt++)
                    mma_tf32(acc[mt][nt], a[mt], b[nt]);
        }
    }

    // epilogue: store C + fused attention-logit partials
    float as0[4], as1[4], ad0[4], ad1[4];
#pragma unroll
    for (int nt = 0; nt < 4; nt++) {
        int c = bn + wn + nt * 8 + 2 * tig;
        as0[nt] = att_s[c]; as1[nt] = att_s[c + 1];
        ad0[nt] = att_d[c]; ad1[nt] = att_d[c + 1];
    }
#pragma unroll
    for (int mt = 0; mt < 4; mt++) {
        int r0 = bm + wm + mt * 16 + g;
        int r1 = r0 + 8;
        float ps0 = 0.f, pd0 = 0.f, ps1 = 0.f, pd1 = 0.f;
#pragma unroll
        for (int nt = 0; nt < 4; nt++) {
            int c = bn + wn + nt * 8 + 2 * tig;
            if (r0 < M) *(float2*)(C + (size_t)r0 * NN + c) = make_float2(acc[mt][nt][0], acc[mt][nt][1]);
            if (r1 < M) *(float2*)(C + (size_t)r1 * NN + c) = make_float2(acc[mt][nt][2], acc[mt][nt][3]);
            ps0 = fmaf(acc[mt][nt][0], as0[nt], fmaf(acc[mt][nt][1], as1[nt], ps0));
            pd0 = fmaf(acc[mt][nt][0], ad0[nt], fmaf(acc[mt][nt][1], ad1[nt], pd0));
            ps1 = fmaf(acc[mt][nt][2], as0[nt], fmaf(acc[mt][nt][3], as1[nt], ps1));
            pd1 = fmaf(acc[mt][nt][2], ad0[nt], fmaf(acc[mt][nt][3], ad1[nt], pd1));
        }
#pragma unroll
        for (int o = 1; o < 4; o <<= 1) {
            ps0 += __shfl_xor_sync(0xffffffffu, ps0, o);
            pd0 += __shfl_xor_sync(0xffffffffu, pd0, o);
            ps1 += __shfl_xor_sync(0xffffffffu, ps1, o);
            pd1 += __shfl_xor_sync(0xffffffffu, pd1, o);
        }
        if (tig == 0) {
            if (r0 < M) { atomicAdd(&g_a1s[r0], ps0); atomicAdd(&g_a1d[r0], pd0); }
            if (r1 < M) { atomicAdd(&g_a1s[r1], ps1); atomicAdd(&g_a1d[r1], pd1); }
        }
    }
}

// ------------------------- pipelined quad GEMM: sum(h3 .* (h3 @ G)) -------------
__global__ __launch_bounds__(256, 2) void mm_quad_pipe(int M) {
    extern __shared__ char smem[];
    __shared__ float red[256];
    const float* A = g_h3;
    const float* B = g_G;
    const int NN = H1, K = H1;
    const uint32_t sb = smem_to_u32(smem);
    const int tid = threadIdx.x;
    const int warp = tid >> 5, lane = tid & 31;
    const int g = lane >> 2, tig = lane & 3;
    const int wm = (warp & 1) * 64, wn = (warp >> 1) * 32;
    const int bm = blockIdx.x * BM, bn = blockIdx.y * BN;
    const int KT = K / BK;

    float acc[4][4][4];
#pragma unroll
    for (int mt = 0; mt < 4; mt++)
#pragma unroll
        for (int nt = 0; nt < 4; nt++)
#pragma unroll
            for (int q = 0; q < 4; q++) acc[mt][nt][q] = 0.f;

    ISSUE_STAGE(0, 0);
    ISSUE_STAGE(1, BK);

    for (int kt = 0; kt < KT; kt++) {
        CP_WAIT1();
        __syncthreads();
        int nxt = kt + 2;
        if (nxt < KT) { ISSUE_STAGE(nxt % NSTG, nxt * BK); }
        else          { CP_COMMIT(); }

        const float* As_f = (const float*)(smem + (kt % NSTG) * STG_BYTES);
        const float* Bs_f = (const float*)(smem + (kt % NSTG) * STG_BYTES + A_BYTES);
#pragma unroll
        for (int ka = 0; ka < 4; ka++) {
            int kb = ka * 8;
            uint32_t a[4][4], b[4][2];
#pragma unroll
            for (int mt = 0; mt < 4; mt++) {
                int m0 = wm + mt * 16 + g;
                a[mt][0] = f2tf(As_f[m0 * APF + kb + tig]);
                a[mt][1] = f2tf(As_f[(m0 + 8) * APF + kb + tig]);
                a[mt][2] = f2tf(As_f[m0 * APF + kb + tig + 4]);
                a[mt][3] = f2tf(As_f[(m0 + 8) * APF + kb + tig + 4]);
            }
#pragma unroll
            for (int nt = 0; nt < 4; nt++) {
                int n0 = wn + nt * 8 + g;
                b[nt][0] = f2tf(Bs_f[(kb + tig) * BPF + n0]);
                b[nt][1] = f2tf(Bs_f[(kb + tig + 4) * BPF + n0]);
            }
#pragma unroll
            for (int mt = 0; mt < 4; mt++)
#pragma unroll
                for (int nt = 0; nt < 4; nt++)
                    mma_tf32(acc[mt][nt], a[mt], b[nt]);
        }
    }

    float part = 0.f;
#pragma unroll
    for (int mt = 0; mt < 4; mt++) {
        int r0 = bm + wm + mt * 16 + g;
        int r1 = r0 + 8;
#pragma unroll
        for (int nt = 0; nt < 4; nt++) {
            int c = bn + wn + nt * 8 + 2 * tig;
            if (r0 < M) {
                float2 h = *(const float2*)(g_h3 + (size_t)r0 * H1 + c);
                part = fmaf(acc[mt][nt][0], h.x, part);
                part = fmaf(acc[mt][nt][1], h.y, part);
            }
            if (r1 < M) {
                float2 h = *(const float2*)(g_h3 + (size_t)r1 * H1 + c);
                part = fmaf(acc[mt][nt][2], h.x, part);
                part = fmaf(acc[mt][nt][3], h.y, part);
            }
        }
    }
    red[tid] = part;
    __syncthreads();
    for (int o = 128; o > 0; o >>= 1) {
        if (tid < o) red[tid] += red[tid + o];
        __syncthreads();
    }
    if (tid == 0) atomicAdd(&g_quad, (double)red[0]);
}

// ------------------------- sum(features^2) -------------------------
__global__ __launch_bounds__(256) void sumf2_kernel(const float* __restrict__ f) {
    __shared__ float red[256];
    const size_t total4 = (size_t)N_NODES * NFEAT / 4;
    size_t idx = (size_t)blockIdx.x * blockDim.x + threadIdx.x;
    size_t stride = (size_t)gridDim.x * blockDim.x;
    float part = 0.f;
    for (size_t i = idx; i < total4; i += stride) {
        float4 v = ((const float4*)f)[i];
        part = fmaf(v.x, v.x, part);
        part = fmaf(v.y, v.y, part);
        part = fmaf(v.z, v.z, part);
        part = fmaf(v.w, v.w, part);
    }
    red[threadIdx.x] = part;
    __syncthreads();
    for (int o = 128; o > 0; o >>= 1) {
        if (threadIdx.x < o) red[threadIdx.x] += red[threadIdx.x + o];
        __syncthreads();
    }
    if (threadIdx.x == 0) atomicAdd(&g_sumf2, (double)red[0]);
}

// ------------------------- CSR build -------------------------
__global__ void count_kernel(const int* __restrict__ ei) {
    int e = blockIdx.x * blockDim.x + threadIdx.x;
    if (e >= ET) return;
    int dst = (e < N_EDGES) ? ei[N_EDGES + e] : (e - N_EDGES);
    atomicAdd(&g_count[dst], 1);
}

__global__ void scan_kernel() {
    __shared__ int part[1024];
    int t = threadIdx.x;
    const int PER = 20;
    int base = t * PER;
    int local[PER];
    int s = 0;
#pragma unroll
    for (int i = 0; i < PER; i++) {
        int idx = base + i;
        int c = (idx < N_NODES) ? g_count[idx] : 0;
        local[i] = s; s += c;
    }
    part[t] = s;
    __syncthreads();
    for (int off = 1; off < 1024; off <<= 1) {
        int v = (t >= off) ? part[t - off] : 0;
        __syncthreads();
        part[t] += v;
        __syncthreads();
    }
    int pre = (t > 0) ? part[t - 1] : 0;
#pragma unroll
    for (int i = 0; i < PER; i++) {
        int idx = base + i;
        if (idx < N_NODES) g_rowptr[idx] = pre + local[i];
    }
    if (t == 1023) g_rowptr[N_NODES] = part[1023];
}

__global__ void fill_kernel(const int* __restrict__ ei) {
    int e = blockIdx.x * blockDim.x + threadIdx.x;
    if (e >= ET) return;
    int src, dst;
    if (e < N_EDGES) { src = ei[e]; dst = ei[N_EDGES + e]; }
    else { src = e - N_EDGES; dst = e - N_EDGES; }
    float z = g_a1s[src] + g_a1d[dst];
    float sg = 1.f / (1.f + expf(-z));
    float ex = expf(sg);                  // softmax numerator (shift-invariant)
    int pos = g_rowptr[dst] + atomicAdd(&g_cursor[dst], 1);
    g_srcs[pos] = src;
    g_exs[pos] = ex;
    atomicAdd(&g_den[dst], ex);
}

// ------------------------- gather #1: h1 = elu(propagate(xw1)) --------------------
// edges staged into warp registers, broadcast via shfl (no per-thread edge LDGs)
__global__ __launch_bounds__(128) void gather_kernel(const float* __restrict__ X,
                                                     float* __restrict__ Out) {
    int i = blockIdx.x;
    int t = threadIdx.x;
    int lane = t & 31;
    int beg = g_rowptr[i], end = g_rowptr[i + 1];
    float4 acc = make_float4(0.f, 0.f, 0.f, 0.f);
    for (int j0 = beg; j0 < end; j0 += 32) {
        int sj = 0; float wj = 0.f;
        if (j0 + lane < end) { sj = g_srcs[j0 + lane]; wj = g_exs[j0 + lane]; }
        int m = min(32, end - j0);
        for (int jj = 0; jj < m; jj++) {
            int s   = __shfl_sync(0xffffffffu, sj, jj);
            float w = __shfl_sync(0xffffffffu, wj, jj);
            float4 v = *(const float4*)(X + (size_t)s * H1 + t * 4);
            acc.x = fmaf(w, v.x, acc.x);
            acc.y = fmaf(w, v.y, acc.y);
            acc.z = fmaf(w, v.z, acc.z);
            acc.w = fmaf(w, v.w, acc.w);
        }
    }
    float inv = 1.f / g_den[i];
    float4 o; float x;
    x = acc.x * inv; o.x = (x > 0.f) ? x : (expf(x) - 1.f);
    x = acc.y * inv; o.y = (x > 0.f) ? x : (expf(x) - 1.f);
    x = acc.z * inv; o.z = (x > 0.f) ? x : (expf(x) - 1.f);
    x = acc.w * inv; o.w = (x > 0.f) ? x : (expf(x) - 1.f);
    *(float4*)(Out + (size_t)i * H1 + t * 4) = o;
}

// ------------------------- gather #2: h3 + cross term sum(h3 .* xw1) --------------
__global__ __launch_bounds__(128) void gather2_kernel(const float* __restrict__ X) {
    __shared__ float red[128];
    int i = blockIdx.x;
    int t = threadIdx.x;
    int lane = t & 31;
    int beg = g_rowptr[i], end = g_rowptr[i + 1];
    float4 acc = make_float4(0.f, 0.f, 0.f, 0.f);
    for (int j0 = beg; j0 < end; j0 += 32) {
        int sj = 0; float wj = 0.f;
        if (j0 + lane < end) { sj = g_srcs[j0 + lane]; wj = g_exs[j0 + lane]; }
        int m = min(32, end - j0);
        for (int jj = 0; jj < m; jj++) {
            int s   = __shfl_sync(0xffffffffu, sj, jj);
            float w = __shfl_sync(0xffffffffu, wj, jj);
            float4 v = *(const float4*)(X + (size_t)s * H1 + t * 4);
            acc.x = fmaf(w, v.x, acc.x);
            acc.y = fmaf(w, v.y, acc.y);
            acc.z = fmaf(w, v.z, acc.z);
            acc.w = fmaf(w, v.w, acc.w);
        }
    }
    float inv = 1.f / g_den[i];
    float4 o; float x;
    x = acc.x * inv; o.x = (x > 0.f) ? x : (expf(x) - 1.f);
    x = acc.y * inv; o.y = (x > 0.f) ? x : (expf(x) - 1.f);
    x = acc.z * inv; o.z = (x > 0.f) ? x : (expf(x) - 1.f);
    x = acc.w * inv; o.w = (x > 0.f) ? x : (expf(x) - 1.f);
    *(float4*)(g_h3 + (size_t)i * H1 + t * 4) = o;

    float4 x1 = *(const float4*)(g_xw1 + (size_t)i * H1 + t * 4);
    float part = o.x * x1.x + o.y * x1.y + o.z * x1.z + o.w * x1.w;
    red[t] = part;
    __syncthreads();
    for (int off = 64; off > 0; off >>= 1) {
        if (t < off) red[t] += red[t + off];
        __syncthreads();
    }
    if (t == 0) atomicAdd(&g_cross, (double)red[0]);
}

// ------------------------- fused h2 + xw3 ----------------------------------------
// per warp: y = h1[i] @ W2 (30), h2n = y/||y||, xw3[i] = h2n @ W2^T (512).
// W2 staged in smem: phase1 row-major halves, phase2 transposed halves.
__global__ __launch_bounds__(256) void h2xw3_kernel(const float* __restrict__ W2) {
    __shared__ float W2s[7800];        // max(256*30, 30*260)
    __shared__ float hrow[8][H1];
    int w = threadIdx.x >> 5, lane = threadIdx.x & 31;
    int tid = threadIdx.x;
    int r = blockIdx.x * 8 + w;

    const float* src = g_h1 + (size_t)r * H1;
    for (int k = lane; k < H1; k += 32) hrow[w][k] = src[k];

    // phase 1: y[j] = sum_k h1[k] * W2[k][j]
    float val = 0.f;
#pragma unroll
    for (int pass = 0; pass < 2; pass++) {
        __syncthreads();
        for (int idx = tid; idx < 256 * H2; idx += 256)
            W2s[idx] = W2[pass * 256 * H2 + idx];
        __syncthreads();
        if (lane < H2) {
            const float* hr = &hrow[w][pass * 256];
#pragma unroll 8
            for (int k = 0; k < 256; k++)
                val = fmaf(hr[k], W2s[k * H2 + lane], val);
        }
    }
    float sq = (lane < H2) ? val * val : 0.f;
#pragma unroll
    for (int off = 16; off > 0; off >>= 1) sq += __shfl_xor_sync(0xffffffffu, sq, off);
    float inv = 1.f / fmaxf(sqrtf(sq), 1e-12f);
    __syncthreads();                    // all warps done with phase-1 W2s
    if (lane < H2) hrow[w][lane] = val * inv;   // h2n overwrites h1 (phase1 done)
    __syncwarp();

    // phase 2: xw3[c] = sum_j h2n[j] * W2[c][j], W2T staged as [j][c_local]
#pragma unroll
    for (int pass = 0; pass < 2; pass++) {
        __syncthreads();
        for (int idx = tid; idx < 256 * H2; idx += 256) {
            int c = idx / H2, j = idx - c * H2;
            W2s[j * 260 + c] = W2[(size_t)(pass * 256 + c) * H2 + j];
        }
        __syncthreads();
#pragma unroll
        for (int q = 0; q < 8; q++) {
            int c = lane + 32 * q;
            float s = 0.f;
#pragma unroll
            for (int j = 0; j < H2; j++)
                s = fmaf(hrow[w][j], W2s[j * 260 + c], s);
            g_xw3[(size_t)r * H1 + pass * 256 + c] = s;
        }
    }
}

// ------------------------- finalize -------------------------
__global__ void finalize_kernel(float* out) {
    double mse = (g_sumf2 - 2.0 * g_cross + g_quad) * (1.0 / ((double)N_NODES * (double)NFEAT));
    out[0] = (float)mse;
}

// ------------------------- launch -------------------------
extern "C" void kernel_launch(void* const* d_in, const int* in_sizes, int n_in,
                              void* d_out, int out_size) {
    const float* features = (const float*)d_in[0];
    const int*   ei       = (const int*)d_in[1];
    const float* W1       = (const float*)d_in[2];
    const float* att_src1 = (const float*)d_in[3];
    const float* att_dst1 = (const float*)d_in[4];
    const float* W2       = (const float*)d_in[5];
    float* out = (float*)d_out;

    cudaFuncSetAttribute(mm_xw1_att,   cudaFuncAttributeMaxDynamicSharedMemorySize, PIPE_SMEM);
    cudaFuncSetAttribute(mm_quad_pipe, cudaFuncAttributeMaxDynamicSharedMemorySize, PIPE_SMEM);

    // 1. init
    init_kernel<<<(N_NODES + 255) / 256, 256>>>();

    // 2. G = W1^T W1
    {
        dim3 grid(H1 / BM, H1 / BN);
        mm_tn_G<<<grid, 256>>>(W1);
    }

    // 3. CSR count
    count_kernel<<<(ET + 255) / 256, 256>>>(ei);

    // 4. xw1 = features @ W1 + fused attention logits   <-- profiled slot
    {
        dim3 grid((N_NODES + BM - 1) / BM, H1 / BN);
        mm_xw1_att<<<grid, 256, PIPE_SMEM>>>(features, W1, g_xw1,
                                             att_src1, att_dst1,
                                             N_NODES, H1, NFEAT);
    }

    // 5. CSR scan
    scan_kernel<<<1, 1024>>>();

    // 6. sum(features^2)
    sumf2_kernel<<<2048, 256>>>(features);

    // 7. CSR fill + softmax numerators (needs a1s/a1d from step 4)
    fill_kernel<<<(ET + 255) / 256, 256>>>(ei);

    // 8. h1 = elu(propagate(xw1))
    gather_kernel<<<N_NODES, 128>>>(g_xw1, g_h1);

    // 9. fused h2 + xw3
    h2xw3_kernel<<<N_NODES / 8, 256>>>(W2);

    // 10. h3 = elu(propagate(xw3)) + cross term
    gather2_kernel<<<N_NODES, 128>>>(g_xw3);

    // 11. quad term: sum(h3 .* (h3 @ G))
    {
        dim3 grid((N_NODES + BM - 1) / BM, H1 / BN);
        mm_quad_pipe<<<grid, 256, PIPE_SMEM>>>(N_NODES);
    }

    // 12. mse
    finalize_kernel<<<1, 1>>>(out);
}